// round 1
// baseline (speedup 1.0000x reference)
#include <cuda_runtime.h>
#include <cuda_bf16.h>

// Problem constants (fixed for this dataset instance)
#define BATCH       256
#define IN_FEAT     20000
#define OUT_FEAT    5000
#define NUM_EDGES   1000000

// ---------------- scratch (no allocation allowed -> __device__ globals) ----
__device__ float g_xt[IN_FEAT * BATCH];        // x transposed: [IN_FEAT][BATCH], 20.48 MB
__device__ int2  g_edge[NUM_EDGES];            // dst-sorted edges: {src, w_as_int}, 8 MB
__device__ int   g_cnt[OUT_FEAT];              // edges per output column
__device__ int   g_start[OUT_FEAT];            // CSR row starts
__device__ int   g_cursor[OUT_FEAT];           // scatter cursors

// ---------------- 0) zero histogram -----------------------------------------
__global__ void zero_cnt_kernel() {
    int i = blockIdx.x * blockDim.x + threadIdx.x;
    if (i < OUT_FEAT) g_cnt[i] = 0;
}

// ---------------- 1) transpose x [B][IN] -> xT [IN][B] ----------------------
__global__ void transpose_kernel(const float* __restrict__ x) {
    __shared__ float tile[32][33];
    int s0 = blockIdx.x * 32;
    int b0 = blockIdx.y * 32;
    int tx = threadIdx.x;    // 0..31
    int ty = threadIdx.y;    // 0..31
    // coalesced read along IN dimension
    tile[ty][tx] = x[(b0 + ty) * IN_FEAT + (s0 + tx)];
    __syncthreads();
    // coalesced write along BATCH dimension
    g_xt[(s0 + ty) * BATCH + (b0 + tx)] = tile[tx][ty];
}

// ---------------- 2) histogram of dst (smem-privatized) ---------------------
__global__ void hist_kernel(const int* __restrict__ dst, int n) {
    __shared__ int h[OUT_FEAT];
    for (int i = threadIdx.x; i < OUT_FEAT; i += blockDim.x) h[i] = 0;
    __syncthreads();
    for (int e = blockIdx.x * blockDim.x + threadIdx.x; e < n;
         e += gridDim.x * blockDim.x) {
        atomicAdd(&h[dst[e]], 1);
    }
    __syncthreads();
    for (int i = threadIdx.x; i < OUT_FEAT; i += blockDim.x) {
        int v = h[i];
        if (v) atomicAdd(&g_cnt[i], v);
    }
}

// ---------------- 3) exclusive scan over 5000 counts (single CTA) -----------
#define SCAN_THREADS 1024
#define SCAN_NPT     5   // 1024*5 = 5120 >= 5000
__global__ void scan_kernel() {
    __shared__ int sh[SCAN_THREADS];
    int t = threadIdx.x;
    int local[SCAN_NPT];
    int sum = 0;
#pragma unroll
    for (int k = 0; k < SCAN_NPT; k++) {
        int idx = t * SCAN_NPT + k;
        int v = (idx < OUT_FEAT) ? g_cnt[idx] : 0;
        local[k] = v;
        sum += v;
    }
    sh[t] = sum;
    __syncthreads();
    // Hillis-Steele inclusive scan over thread sums
    for (int off = 1; off < SCAN_THREADS; off <<= 1) {
        int v = (t >= off) ? sh[t - off] : 0;
        __syncthreads();
        sh[t] += v;
        __syncthreads();
    }
    int run = sh[t] - sum;  // exclusive prefix for this thread
#pragma unroll
    for (int k = 0; k < SCAN_NPT; k++) {
        int idx = t * SCAN_NPT + k;
        if (idx < OUT_FEAT) {
            g_start[idx]  = run;
            g_cursor[idx] = run;
            run += local[k];
        }
    }
}

// ---------------- 4) scatter edges into CSR buckets --------------------------
__global__ void scatter_kernel(const int* __restrict__ src,
                               const int* __restrict__ dst,
                               const float* __restrict__ w, int n) {
    int e = blockIdx.x * blockDim.x + threadIdx.x;
    if (e < n) {
        int d = dst[e];
        int pos = atomicAdd(&g_cursor[d], 1);
        g_edge[pos] = make_int2(src[e], __float_as_int(w[e]));
    }
}

// ---------------- 5) main SpMM: one column per 64-thread group ---------------
// CTA = 256 threads = 4 groups; each group owns one output column.
// Thread t in group holds batch elements [4t, 4t+3] (float4 of xT row).
__global__ __launch_bounds__(256) void spmm_kernel(const float* __restrict__ bias,
                                                   float* __restrict__ out) {
    int g = threadIdx.x >> 6;            // group 0..3
    int t = threadIdx.x & 63;            // lane in group (0..63)
    int col = blockIdx.x * 4 + g;

    const float4* __restrict__ xt4 = (const float4*)g_xt;   // [IN_FEAT][64]
    int beg = g_start[col];
    int n   = g_cnt[col];
    const int2* ep = g_edge + beg;

    float4 acc = make_float4(0.f, 0.f, 0.f, 0.f);

    int j = 0;
    for (; j + 4 <= n; j += 4) {
        int2 e0 = __ldg(ep + j + 0);
        int2 e1 = __ldg(ep + j + 1);
        int2 e2 = __ldg(ep + j + 2);
        int2 e3 = __ldg(ep + j + 3);
        float4 v0 = xt4[e0.x * 64 + t];
        float4 v1 = xt4[e1.x * 64 + t];
        float4 v2 = xt4[e2.x * 64 + t];
        float4 v3 = xt4[e3.x * 64 + t];
        float w0 = __int_as_float(e0.y);
        float w1 = __int_as_float(e1.y);
        float w2 = __int_as_float(e2.y);
        float w3 = __int_as_float(e3.y);
        acc.x += w0 * v0.x; acc.y += w0 * v0.y; acc.z += w0 * v0.z; acc.w += w0 * v0.w;
        acc.x += w1 * v1.x; acc.y += w1 * v1.y; acc.z += w1 * v1.z; acc.w += w1 * v1.w;
        acc.x += w2 * v2.x; acc.y += w2 * v2.y; acc.z += w2 * v2.z; acc.w += w2 * v2.w;
        acc.x += w3 * v3.x; acc.y += w3 * v3.y; acc.z += w3 * v3.z; acc.w += w3 * v3.w;
    }
    for (; j < n; j++) {
        int2 e = __ldg(ep + j);
        float4 v = xt4[e.x * 64 + t];
        float w0 = __int_as_float(e.y);
        acc.x += w0 * v.x; acc.y += w0 * v.y; acc.z += w0 * v.z; acc.w += w0 * v.w;
    }

    float bb = __ldg(bias + col);

    // stage tanh(acc + bias) in smem, then emit coalesced-ish float4 stores
    __shared__ float sOut[4][BATCH];
    sOut[g][4 * t + 0] = tanhf(acc.x + bb);
    sOut[g][4 * t + 1] = tanhf(acc.y + bb);
    sOut[g][4 * t + 2] = tanhf(acc.z + bb);
    sOut[g][4 * t + 3] = tanhf(acc.w + bb);
    __syncthreads();

    // thread i = batch index b writes out[b][4*blk .. 4*blk+3] as one float4
    int b = threadIdx.x;
    float4 val = make_float4(sOut[0][b], sOut[1][b], sOut[2][b], sOut[3][b]);
    float4* out4 = (float4*)out;                 // row stride = 5000/4 = 1250
    out4[b * (OUT_FEAT / 4) + blockIdx.x] = val;
}

// ---------------- launch ------------------------------------------------------
extern "C" void kernel_launch(void* const* d_in, const int* in_sizes, int n_in,
                              void* d_out, int out_size) {
    const float* x    = (const float*)d_in[0];
    const int*   src  = (const int*)  d_in[1];
    const int*   dst  = (const int*)  d_in[2];
    const float* w    = (const float*)d_in[3];
    const float* bias = (const float*)d_in[4];
    float* out = (float*)d_out;

    int E = in_sizes[1];   // NUM_EDGES

    zero_cnt_kernel<<<(OUT_FEAT + 255) / 256, 256>>>();
    transpose_kernel<<<dim3(IN_FEAT / 32, BATCH / 32), dim3(32, 32)>>>(x);
    hist_kernel<<<64, 1024>>>(dst, E);
    scan_kernel<<<1, SCAN_THREADS>>>();
    scatter_kernel<<<(E + 255) / 256, 256>>>(src, dst, w, E);
    spmm_kernel<<<OUT_FEAT / 4, 256>>>(bias, out);
}